// round 12
// baseline (speedup 1.0000x reference)
#include <cuda_runtime.h>
#include <math.h>

// Split-KV (flash-decoding) stage-2 merge. B=256, H=32, S=16, D=128, fp32.
//
// R11 = R10 resubmitted (round 10 bench was a broker infra failure; the
// design is untested). Rationale from R9 ncu (regs 32, occ 57%, DRAM 41%,
// issue 25% — nothing saturated): the binding term is the serial DRAM
// round structure (4-wide batches => heavy warps run 4 dependent ~600cy
// rounds). Fix: split D (not s) across TWO warps per head, float2 lanes:
//   * all 16 row loads in flight in ONE round, only 32 buffer regs
//   * no cross-warp combine (each warp owns its 64-elem D-slice outright)
//   * 16384 warps = 2x R9 concurrency
//   * paired warps read adjacent 64B halves of the same 128B lines
// Kept: exact per-load predication, cycle-0 LSE/s0/s1 issue, float
// ceil-divs (exact for seq<=8192, splits<=16), half-warp reductions.

#define B_DIM 256
#define H_DIM 32
#define LOG2E 1.4426950408889634f

__global__ __launch_bounds__(64)
void splitkv_merge_kernel(const float* __restrict__ att_out,
                          const float* __restrict__ att_lse,
                          const int*   __restrict__ kv_indptr,
                          const int*   __restrict__ num_kv_splits,
                          float*       __restrict__ out)
{
    const unsigned tid  = threadIdx.x;
    const unsigned lane = tid & 31u;
    const unsigned half = tid >> 5;            // warp-in-block = D-half (0/1)
    const unsigned hid  = blockIdx.x;          // one head per 64-thread block
    const unsigned b    = hid >> 5;            // H == 32

    // float2 view: row stride = 64 float2 (512B, fits LDG immediate offsets);
    // head base = hid*16*64, this warp's D-half at +half*32.
    const float2* __restrict__ src =
        reinterpret_cast<const float2*>(att_out) + hid * 1024u + half * 32u + lane;

    // ---- cycle-0 issue group (independent of the geometry chain) ----
    float2 v0 = src[0 * 64];                   // s=0: always valid
    float2 v1 = src[1 * 64];                   // s=1: w=0 kills it if nv==1

    float lse = -INFINITY;
    if (lane < 16u)
        lse = att_lse[hid * 16u + lane];

    const int ip0 = kv_indptr[b];
    const int ip1 = kv_indptr[b + 1];
    const unsigned splits = (unsigned)num_kv_splits[b];

    // ---- geometry via exact float ceil-divs (seq<=8192, splits<=16) ----
    const unsigned seq = (unsigned)(ip1 - ip0);
    const float fseq = __uint2float_rn(seq);
    const unsigned c1 = (unsigned)ceilf(fseq / __uint2float_rn(splits));
    const unsigned per_split = (c1 + 31u) & ~31u;
    const unsigned nv =
        (unsigned)ceilf(fseq / __uint2float_rn(per_split));   // 1..16 prefix

    // ---- ALL remaining row loads, front-batched, individually predicated ----
    float2 z = make_float2(0.f, 0.f);
    float2 v2 = z, v3 = z, v4 = z, v5 = z, v6 = z, v7 = z;
    float2 v8 = z, v9 = z, v10 = z, v11 = z, v12 = z, v13 = z, v14 = z, v15 = z;

    if (2u < nv) {                 // warp-uniform skip: nv<=2 loads nothing here
        v2 = src[2 * 64];
        if (3u < nv) v3 = src[3 * 64];
        if (4u < nv) v4 = src[4 * 64];
        if (5u < nv) v5 = src[5 * 64];
        if (6u < nv) v6 = src[6 * 64];
        if (7u < nv) v7 = src[7 * 64];
        if (8u < nv) {             // warp-uniform skip for the top half
            v8 = src[8 * 64];
            if ( 9u < nv) v9  = src[ 9 * 64];
            if (10u < nv) v10 = src[10 * 64];
            if (11u < nv) v11 = src[11 * 64];
            if (12u < nv) v12 = src[12 * 64];
            if (13u < nv) v13 = src[13 * 64];
            if (14u < nv) v14 = src[14 * 64];
            if (15u < nv) v15 = src[15 * 64];
        }
    }

    // ---- weights: 4-step low-half reductions + single broadcast ----
    if (lane >= nv) lse = -INFINITY;

    float m = lse;
    #pragma unroll
    for (int o = 8; o > 0; o >>= 1)
        m = fmaxf(m, __shfl_xor_sync(0xffffffffu, m, o));

    const float w = (lane < nv) ? exp2f((lse - m) * LOG2E) : 0.0f;

    float esum = w;
    #pragma unroll
    for (int o = 8; o > 0; o >>= 1)
        esum += __shfl_xor_sync(0xffffffffu, esum, o);

    const float inv_esum = __shfl_sync(0xffffffffu, 1.0f / esum, 0);

    // ---- accumulate: invalid rows have v=0 AND w=0 -> branch-free ----
    float ws = __shfl_sync(0xffffffffu, w, 0);
    float2 acc;
    acc.x = ws * v0.x;
    acc.y = ws * v0.y;

#define ACC(S, V)                                            \
    ws = __shfl_sync(0xffffffffu, w, S);                     \
    acc.x = fmaf(ws, V.x, acc.x);                            \
    acc.y = fmaf(ws, V.y, acc.y);

    ACC(1,  v1)  ACC(2,  v2)  ACC(3,  v3)  ACC(4,  v4)
    ACC(5,  v5)  ACC(6,  v6)  ACC(7,  v7)  ACC(8,  v8)
    ACC(9,  v9)  ACC(10, v10) ACC(11, v11) ACC(12, v12)
    ACC(13, v13) ACC(14, v14) ACC(15, v15)
#undef ACC

    acc.x *= inv_esum;
    acc.y *= inv_esum;

    reinterpret_cast<float2*>(out)[hid * 64u + half * 32u + lane] = acc;
}

extern "C" void kernel_launch(void* const* d_in, const int* in_sizes, int n_in,
                              void* d_out, int out_size)
{
    const float* att_out       = (const float*)d_in[0];
    const float* att_lse       = (const float*)d_in[1];
    // d_in[2] = q, d_in[3] = v_buffer : unused (shape-only in the reference)
    const int*   kv_indptr     = (const int*)d_in[4];
    const int*   num_kv_splits = (const int*)d_in[5];
    float*       out           = (float*)d_out;

    // one head per 64-thread block (2 warps = 2 D-halves) -> 8192 blocks
    splitkv_merge_kernel<<<B_DIM * H_DIM, 64>>>(att_out, att_lse,
                                                kv_indptr, num_kv_splits, out);
}

// round 13
// speedup vs baseline: 1.2500x; 1.2500x over previous
#include <cuda_runtime.h>
#include <math.h>

// Split-KV (flash-decoding) stage-2 merge. B=256, H=32, S=16, D=128, fp32.
//
// R12 = R9 skeleton (the proven law: 1 warp/head, float4, shfl-held
// weights, low regs, low issue) with ONE structural change: two 8-deep
// load rounds instead of four 4-deep rounds. Heavy warps (nv=16) now pay
// 2 dependent ~600cy DRAM rounds, not 4. Instruction count identical to
// R9; buffers are individually named (no arrays -> no local-mem risk);
// peak live set = 8 float4 buffers + acc ~= 46-50 regs (cap ~65% occ).
// Kept: exact per-load predication, cycle-0 LSE/s0/s1 issue, float
// ceil-divs (exact for seq<=8192, splits<=16), half-warp reductions,
// 128-thread blocks (R5's occupancy sweet spot).

#define B_DIM 256
#define H_DIM 32
#define LOG2E 1.4426950408889634f

__global__ __launch_bounds__(128)
void splitkv_merge_kernel(const float* __restrict__ att_out,
                          const float* __restrict__ att_lse,
                          const int*   __restrict__ kv_indptr,
                          const int*   __restrict__ num_kv_splits,
                          float*       __restrict__ out)
{
    const unsigned hid  = (blockIdx.x * 128u + threadIdx.x) >> 5;   // (b,h)
    const unsigned lane = threadIdx.x & 31u;
    const unsigned b    = hid >> 5;                                 // H == 32

    const float4* __restrict__ src =
        reinterpret_cast<const float4*>(att_out) + hid * 512u + lane;

    // ---- cycle-0 issue group (independent of the geometry chain) ----
    float4 v0 = src[0 * 32];                    // s=0: always valid
    float4 v1 = src[1 * 32];                    // s=1: w=0 kills it if nv==1

    float lse = -INFINITY;
    if (lane < 16u)
        lse = att_lse[hid * 16u + lane];

    const int ip0 = kv_indptr[b];
    const int ip1 = kv_indptr[b + 1];
    const unsigned splits = (unsigned)num_kv_splits[b];

    // ---- geometry via exact float ceil-divs (seq<=8192, splits<=16) ----
    const unsigned seq = (unsigned)(ip1 - ip0);
    const float fseq = __uint2float_rn(seq);
    const unsigned c1 = (unsigned)ceilf(fseq / __uint2float_rn(splits));
    const unsigned per_split = (c1 + 31u) & ~31u;
    const unsigned nv =
        (unsigned)ceilf(fseq / __uint2float_rn(per_split));   // 1..16 prefix

    // ---- round 1 remainder: s=2..7, front-batched, predicated ----
    const float4 z = make_float4(0.f, 0.f, 0.f, 0.f);
    float4 v2 = z, v3 = z, v4 = z, v5 = z, v6 = z, v7 = z;
    if (2u < nv) {                              // warp-uniform skip
        v2 = src[2 * 32];
        if (3u < nv) v3 = src[3 * 32];
        if (4u < nv) v4 = src[4 * 32];
        if (5u < nv) v5 = src[5 * 32];
        if (6u < nv) v6 = src[6 * 32];
        if (7u < nv) v7 = src[7 * 32];
    }

    // ---- weights: 4-step low-half reductions + single broadcast ----
    if (lane >= nv) lse = -INFINITY;

    float m = lse;
    #pragma unroll
    for (int o = 8; o > 0; o >>= 1)
        m = fmaxf(m, __shfl_xor_sync(0xffffffffu, m, o));

    const float w = (lane < nv) ? exp2f((lse - m) * LOG2E) : 0.0f;

    float esum = w;
    #pragma unroll
    for (int o = 8; o > 0; o >>= 1)
        esum += __shfl_xor_sync(0xffffffffu, esum, o);

    const float inv_esum = __shfl_sync(0xffffffffu, 1.0f / esum, 0);

    // ---- consume round 1 (s=0..7): invalid rows have v=0 AND w=0 ----
    float ws = __shfl_sync(0xffffffffu, w, 0);
    float4 acc;
    acc.x = ws * v0.x; acc.y = ws * v0.y;
    acc.z = ws * v0.z; acc.w = ws * v0.w;

#define ACC(S, V)                                            \
    ws = __shfl_sync(0xffffffffu, w, S);                     \
    acc.x = fmaf(ws, V.x, acc.x);                            \
    acc.y = fmaf(ws, V.y, acc.y);                            \
    acc.z = fmaf(ws, V.z, acc.z);                            \
    acc.w = fmaf(ws, V.w, acc.w);

    ACC(1, v1) ACC(2, v2) ACC(3, v3) ACC(4, v4)
    ACC(5, v5) ACC(6, v6) ACC(7, v7)

    // ---- round 2 (s=8..15): reuse the same 8 buffers ----
    if (8u < nv) {                              // warp-uniform skip
        v0 = src[8 * 32];
        v1 = v2 = v3 = v4 = v5 = v6 = v7 = z;
        if ( 9u < nv) v1 = src[ 9 * 32];
        if (10u < nv) v2 = src[10 * 32];
        if (11u < nv) v3 = src[11 * 32];
        if (12u < nv) v4 = src[12 * 32];
        if (13u < nv) v5 = src[13 * 32];
        if (14u < nv) v6 = src[14 * 32];
        if (15u < nv) v7 = src[15 * 32];

        ACC( 8, v0) ACC( 9, v1) ACC(10, v2) ACC(11, v3)
        ACC(12, v4) ACC(13, v5) ACC(14, v6) ACC(15, v7)
    }
#undef ACC

    acc.x *= inv_esum;
    acc.y *= inv_esum;
    acc.z *= inv_esum;
    acc.w *= inv_esum;

    reinterpret_cast<float4*>(out)[hid * 32u + lane] = acc;
}

extern "C" void kernel_launch(void* const* d_in, const int* in_sizes, int n_in,
                              void* d_out, int out_size)
{
    const float* att_out       = (const float*)d_in[0];
    const float* att_lse       = (const float*)d_in[1];
    // d_in[2] = q, d_in[3] = v_buffer : unused (shape-only in the reference)
    const int*   kv_indptr     = (const int*)d_in[4];
    const int*   num_kv_splits = (const int*)d_in[5];
    float*       out           = (float*)d_out;

    // 8192 head-warps, 4 warps per 128-thread block -> 2048 blocks exact
    splitkv_merge_kernel<<<(B_DIM * H_DIM) / 4, 128>>>(att_out, att_lse,
                                                       kv_indptr, num_kv_splits, out);
}